// round 1
// baseline (speedup 1.0000x reference)
#include <cuda_runtime.h>
#include <cstdint>

#define B_   8
#define N_   2048
#define DIN  256
#define HID  64
#define TI   64
#define TJ   32

// Scratch (device globals — no allocation allowed)
__device__ float g_Wh[B_ * N_ * HID];                 // 4 MB
__device__ float g_f1[B_ * N_], g_f2[B_ * N_];
__device__ float g_E1[B_ * N_], g_F1[B_ * N_];
__device__ float g_E2[B_ * N_], g_F2[B_ * N_];

// Packed f32x2 FMA (Blackwell FFMA2): d = a*b + d, elementwise on 2 packed f32
__device__ __forceinline__ void ffma2(unsigned long long& d,
                                      unsigned long long a,
                                      unsigned long long b) {
    asm("fma.rn.f32x2 %0, %1, %2, %0;" : "+l"(d) : "l"(a), "l"(b));
}

__device__ __forceinline__ float2 unpack2(unsigned long long v) {
    float2 r;
    r.x = __uint_as_float((unsigned)(v & 0xffffffffull));
    r.y = __uint_as_float((unsigned)(v >> 32));
    return r;
}

// ---------------------------------------------------------------------------
// Kernel A: Wh = X @ W   (16384 x 256) @ (256 x 64)
// Block: 64 rows x 64 cols, 256 threads, thread tile 4x4, K-tiles of 32.
// ---------------------------------------------------------------------------
__global__ __launch_bounds__(256) void gemm_wh(const float* __restrict__ X,
                                               const float* __restrict__ W) {
    __shared__ __align__(16) float Xs[64][36];   // pad 36 (144B rows, 16B aligned)
    __shared__ __align__(16) float Ws[32][64];

    const int tid = threadIdx.x;
    const int tx = tid & 15;    // 4 h each
    const int ty = tid >> 4;    // 4 rows each
    const int r0 = blockIdx.x * 64;

    float acc[4][4];
#pragma unroll
    for (int i = 0; i < 4; i++)
#pragma unroll
        for (int j = 0; j < 4; j++) acc[i][j] = 0.f;

    for (int k0 = 0; k0 < DIN; k0 += 32) {
#pragma unroll
        for (int q = 0; q < 2; q++) {
            int f = q * 256 + tid;
            int r = f >> 3, kc = (f & 7) << 2;
            *(float4*)&Xs[r][kc] =
                *(const float4*)(X + (size_t)(r0 + r) * DIN + k0 + kc);
        }
#pragma unroll
        for (int q = 0; q < 2; q++) {
            int f = q * 256 + tid;
            int k = f >> 4, hc = (f & 15) << 2;
            *(float4*)&Ws[k][hc] =
                *(const float4*)(W + (size_t)(k0 + k) * HID + hc);
        }
        __syncthreads();
#pragma unroll
        for (int k = 0; k < 32; k++) {
            float4 wv = *(float4*)&Ws[k][tx << 2];
#pragma unroll
            for (int rr = 0; rr < 4; rr++) {
                float xv = Xs[(ty << 2) + rr][k];
                acc[rr][0] += xv * wv.x;
                acc[rr][1] += xv * wv.y;
                acc[rr][2] += xv * wv.z;
                acc[rr][3] += xv * wv.w;
            }
        }
        __syncthreads();
    }
#pragma unroll
    for (int rr = 0; rr < 4; rr++) {
        float4 v = make_float4(acc[rr][0], acc[rr][1], acc[rr][2], acc[rr][3]);
        *(float4*)&g_Wh[(size_t)(r0 + (ty << 2) + rr) * HID + (tx << 2)] = v;
    }
}

// ---------------------------------------------------------------------------
// Kernel B: f1 = Wh@a1, f2 = Wh@a2, and the 4 exponential factors per node.
// One warp per row.
// ---------------------------------------------------------------------------
__global__ __launch_bounds__(256) void compute_f(const float* __restrict__ a) {
    const int row = blockIdx.x * 8 + (threadIdx.x >> 5);
    const int lane = threadIdx.x & 31;
    const float* wh = g_Wh + (size_t)row * HID;
    float w0 = wh[lane], w1 = wh[lane + 32];
    float f1 = w0 * a[lane] + w1 * a[lane + 32];
    float f2 = w0 * a[HID + lane] + w1 * a[HID + lane + 32];
#pragma unroll
    for (int s = 16; s > 0; s >>= 1) {
        f1 += __shfl_xor_sync(0xffffffffu, f1, s);
        f2 += __shfl_xor_sync(0xffffffffu, f2, s);
    }
    if (lane == 0) {
        g_f1[row] = f1;
        g_f2[row] = f2;
        g_E1[row] = __expf(f1);
        g_F1[row] = __expf(0.2f * f1);
        g_E2[row] = __expf(f2);
        g_F2[row] = __expf(0.2f * f2);
    }
}

// ---------------------------------------------------------------------------
// Main kernel: fused masked-softmax attention + h' = att @ Wh
// Grid: (N/TI, B) = (32, 8). Block 256 threads, two cooperative roles:
//   stage1: (wid 0..7, lane 0..31) -> compute w tile [TI x TJ] into smem,
//           stored pre-duplicated as float2 (w,w) for FFMA2 consumption.
//   stage2: (tx 0..7 -> 8 h, ty 0..31 -> rows ty & ty+32) -> FFMA2 GEMM.
// exp() never appears in the inner loop: w = adj ? (x>0 ? E1*E2 : F1*F2) : 0.
// ---------------------------------------------------------------------------
__global__ __launch_bounds__(256) void gat_main(const int* __restrict__ adj,
                                                float* __restrict__ out) {
    __shared__ __align__(16) float2 ws[TJ][TI + 1];  // (w,w) pairs, +1 pad
    __shared__ __align__(16) float Whs[TJ][HID];
    __shared__ float f2s[TJ], E2s[TJ], F2s[TJ];
    __shared__ float ls[TI];

    const int tid = threadIdx.x;
    const int lane = tid & 31, wid = tid >> 5;  // stage1 role
    const int tx = tid & 7, ty = tid >> 3;      // stage2 role
    const int b = blockIdx.y;
    const int i0 = blockIdx.x * TI;
    const int base = b * N_;

    const int* adjb = adj + (size_t)b * N_ * N_ + (size_t)i0 * N_;
    const float* Whb = g_Wh + (size_t)b * N_ * HID;

    float f1r[8], E1r[8], F1r[8], lacc[8];
#pragma unroll
    for (int p = 0; p < 8; p++) {
        int gi = base + i0 + p * 8 + wid;
        f1r[p] = g_f1[gi];
        E1r[p] = g_E1[gi];
        F1r[p] = g_F1[gi];
        lacc[p] = 0.f;
    }

    unsigned long long acc[2][4];
#pragma unroll
    for (int i = 0; i < 2; i++)
#pragma unroll
        for (int q = 0; q < 4; q++) acc[i][q] = 0ull;  // packed (0.f, 0.f)

    // Prefetch adj for first tile
    int av[8];
#pragma unroll
    for (int p = 0; p < 8; p++)
        av[p] = adjb[(size_t)(p * 8 + wid) * N_ + lane];

    for (int j0 = 0; j0 < N_; j0 += TJ) {
        __syncthreads();  // previous tile's consumers done

        if (tid < TJ) {
            int gj = base + j0 + tid;
            f2s[tid] = g_f2[gj];
            E2s[tid] = g_E2[gj];
            F2s[tid] = g_F2[gj];
        }
#pragma unroll
        for (int q = 0; q < 2; q++) {
            int f = q * 256 + tid;
            int j = f >> 4, hc = (f & 15) << 2;
            *(float4*)&Whs[j][hc] =
                *(const float4*)(Whb + (size_t)(j0 + j) * HID + hc);
        }
        __syncthreads();

        // stage1: attention weights for this tile
#pragma unroll
        for (int p = 0; p < 8; p++) {
            int i = p * 8 + wid;
            float x = f1r[p] + f2s[lane];
            float w = (x > 0.f) ? (E1r[p] * E2s[lane]) : (F1r[p] * F2s[lane]);
            w = (av[p] > 0) ? w : 0.f;
            lacc[p] += w;
            ws[lane][i] = make_float2(w, w);
        }
        // prefetch adj for next tile (latency hides under stage2)
        if (j0 + TJ < N_) {
#pragma unroll
            for (int p = 0; p < 8; p++)
                av[p] = adjb[(size_t)(p * 8 + wid) * N_ + j0 + TJ + lane];
        }
        __syncthreads();

        // stage2: acc += w ⊗ Wh  (packed f32x2 FMAs, 16 flops/FFMA2-pair-step)
#pragma unroll
        for (int j = 0; j < TJ; j++) {
            unsigned long long w0 = *(const unsigned long long*)&ws[j][ty];
            unsigned long long w1 = *(const unsigned long long*)&ws[j][ty + 32];
            ulonglong2 A = *(const ulonglong2*)&Whs[j][tx * 8];
            ulonglong2 Bv = *(const ulonglong2*)&Whs[j][tx * 8 + 4];
            ffma2(acc[0][0], w0, A.x);
            ffma2(acc[0][1], w0, A.y);
            ffma2(acc[0][2], w0, Bv.x);
            ffma2(acc[0][3], w0, Bv.y);
            ffma2(acc[1][0], w1, A.x);
            ffma2(acc[1][1], w1, A.y);
            ffma2(acc[1][2], w1, Bv.x);
            ffma2(acc[1][3], w1, Bv.y);
        }
    }

    // reduce softmax denominators and publish
#pragma unroll
    for (int p = 0; p < 8; p++) {
        float v = lacc[p];
#pragma unroll
        for (int s = 16; s > 0; s >>= 1) v += __shfl_xor_sync(0xffffffffu, v, s);
        if (lane == 0) ls[p * 8 + wid] = v;
    }
    __syncthreads();

    const float r0 = __fdividef(1.f, ls[ty]);
    const float r1 = __fdividef(1.f, ls[ty + 32]);

    float* o0 = out + (size_t)(base + i0 + ty) * HID + tx * 8;
    float* o1 = out + (size_t)(base + i0 + ty + 32) * HID + tx * 8;

    {
        float2 a0 = unpack2(acc[0][0]), a1 = unpack2(acc[0][1]);
        float2 a2 = unpack2(acc[0][2]), a3 = unpack2(acc[0][3]);
        *(float4*)o0       = make_float4(a0.x * r0, a0.y * r0, a1.x * r0, a1.y * r0);
        *(float4*)(o0 + 4) = make_float4(a2.x * r0, a2.y * r0, a3.x * r0, a3.y * r0);
    }
    {
        float2 a0 = unpack2(acc[1][0]), a1 = unpack2(acc[1][1]);
        float2 a2 = unpack2(acc[1][2]), a3 = unpack2(acc[1][3]);
        *(float4*)o1       = make_float4(a0.x * r1, a0.y * r1, a1.x * r1, a1.y * r1);
        *(float4*)(o1 + 4) = make_float4(a2.x * r1, a2.y * r1, a3.x * r1, a3.y * r1);
    }
}

// ---------------------------------------------------------------------------
extern "C" void kernel_launch(void* const* d_in, const int* in_sizes, int n_in,
                              void* d_out, int out_size) {
    const float* X  = (const float*)d_in[0];   // node_features [8,2048,256]
    const int*   A  = (const int*)d_in[1];     // adj [8,2048,2048]
    const float* W  = (const float*)d_in[2];   // W [256,64]
    const float* av = (const float*)d_in[3];   // a [128,1]
    float* out = (float*)d_out;                // [8,2048,64] f32

    gemm_wh<<<(B_ * N_) / 64, 256>>>(X, W);
    compute_f<<<(B_ * N_) / 8, 256>>>(av);
    gat_main<<<dim3(N_ / TI, B_), 256>>>(A, out);
}

// round 2
// speedup vs baseline: 1.0600x; 1.0600x over previous
#include <cuda_runtime.h>
#include <cstdint>

#define B_   8
#define N_   2048
#define DIN  256
#define HID  64
#define TI   64
#define TJ   32
#define NT   (N_ / TJ)   // 64 tiles

// Scratch (device globals — no allocation allowed)
__device__ float g_Wh[B_ * N_ * HID];                 // 4 MB
__device__ float g_f1[B_ * N_], g_f2[B_ * N_];
__device__ float g_E1[B_ * N_], g_F1[B_ * N_];
__device__ float g_E2[B_ * N_], g_F2[B_ * N_];

// Packed f32x2 FMA (Blackwell FFMA2): d = a*b + d, elementwise on 2 packed f32
__device__ __forceinline__ void ffma2(unsigned long long& d,
                                      unsigned long long a,
                                      unsigned long long b) {
    asm("fma.rn.f32x2 %0, %1, %2, %0;" : "+l"(d) : "l"(a), "l"(b));
}

__device__ __forceinline__ float2 unpack2(unsigned long long v) {
    float2 r;
    r.x = __uint_as_float((unsigned)(v & 0xffffffffull));
    r.y = __uint_as_float((unsigned)(v >> 32));
    return r;
}

// ---------------------------------------------------------------------------
// Kernel A: Wh = X @ W   (16384 x 256) @ (256 x 64)
// Double-buffered SMEM K-tiles (32), register prefetch, 1 barrier per tile.
// ---------------------------------------------------------------------------
__global__ __launch_bounds__(256) void gemm_wh(const float* __restrict__ X,
                                               const float* __restrict__ W) {
    __shared__ __align__(16) float Xs[2][64][36];
    __shared__ __align__(16) float Ws[2][32][64];

    const int tid = threadIdx.x;
    const int tx = tid & 15;    // 4 h each
    const int ty = tid >> 4;    // 4 rows each
    const int r0 = blockIdx.x * 64;

    // load indices
    const int xr = tid >> 3, xk = (tid & 7) << 2;        // q stride: +32 rows? no:
    // q=0: f=tid      -> r=tid>>3 (0..31),  kc=(tid&7)*4
    // q=1: f=256+tid  -> r=32+(tid>>3),     kc same
    const int wk = tid >> 4, wh_ = (tid & 15) << 2;      // q=0: k=tid>>4 (0..15); q=1: k=16+

    float acc[4][4];
#pragma unroll
    for (int i = 0; i < 4; i++)
#pragma unroll
        for (int j = 0; j < 4; j++) acc[i][j] = 0.f;

    float4 xv0, xv1, wv0, wv1;
    // prologue: k-tile 0
    xv0 = *(const float4*)(X + (size_t)(r0 + xr) * DIN + xk);
    xv1 = *(const float4*)(X + (size_t)(r0 + 32 + xr) * DIN + xk);
    wv0 = *(const float4*)(W + (size_t)wk * HID + wh_);
    wv1 = *(const float4*)(W + (size_t)(16 + wk) * HID + wh_);
    *(float4*)&Xs[0][xr][xk]      = xv0;
    *(float4*)&Xs[0][32 + xr][xk] = xv1;
    *(float4*)&Ws[0][wk][wh_]      = wv0;
    *(float4*)&Ws[0][16 + wk][wh_] = wv1;
    __syncthreads();

    for (int kt = 0; kt < 8; kt++) {
        const int cur = kt & 1, nxt = cur ^ 1;
        if (kt < 7) {
            const int k0 = (kt + 1) * 32;
            xv0 = *(const float4*)(X + (size_t)(r0 + xr) * DIN + k0 + xk);
            xv1 = *(const float4*)(X + (size_t)(r0 + 32 + xr) * DIN + k0 + xk);
            wv0 = *(const float4*)(W + (size_t)(k0 + wk) * HID + wh_);
            wv1 = *(const float4*)(W + (size_t)(k0 + 16 + wk) * HID + wh_);
        }
#pragma unroll
        for (int k = 0; k < 32; k++) {
            float4 wv = *(float4*)&Ws[cur][k][tx << 2];
#pragma unroll
            for (int rr = 0; rr < 4; rr++) {
                float xv = Xs[cur][(ty << 2) + rr][k];
                acc[rr][0] += xv * wv.x;
                acc[rr][1] += xv * wv.y;
                acc[rr][2] += xv * wv.z;
                acc[rr][3] += xv * wv.w;
            }
        }
        if (kt < 7) {
            *(float4*)&Xs[nxt][xr][xk]      = xv0;
            *(float4*)&Xs[nxt][32 + xr][xk] = xv1;
            *(float4*)&Ws[nxt][wk][wh_]      = wv0;
            *(float4*)&Ws[nxt][16 + wk][wh_] = wv1;
        }
        __syncthreads();
    }
#pragma unroll
    for (int rr = 0; rr < 4; rr++) {
        float4 v = make_float4(acc[rr][0], acc[rr][1], acc[rr][2], acc[rr][3]);
        *(float4*)&g_Wh[(size_t)(r0 + (ty << 2) + rr) * HID + (tx << 2)] = v;
    }
}

// ---------------------------------------------------------------------------
// Kernel B: f1 = Wh@a1, f2 = Wh@a2, plus the 4 exponential factors per node.
// ---------------------------------------------------------------------------
__global__ __launch_bounds__(256) void compute_f(const float* __restrict__ a) {
    const int row = blockIdx.x * 8 + (threadIdx.x >> 5);
    const int lane = threadIdx.x & 31;
    const float* wh = g_Wh + (size_t)row * HID;
    float w0 = wh[lane], w1 = wh[lane + 32];
    float f1 = w0 * a[lane] + w1 * a[lane + 32];
    float f2 = w0 * a[HID + lane] + w1 * a[HID + lane + 32];
#pragma unroll
    for (int s = 16; s > 0; s >>= 1) {
        f1 += __shfl_xor_sync(0xffffffffu, f1, s);
        f2 += __shfl_xor_sync(0xffffffffu, f2, s);
    }
    if (lane == 0) {
        g_f1[row] = f1;
        g_f2[row] = f2;
        g_E1[row] = __expf(f1);
        g_F1[row] = __expf(0.2f * f1);
        g_E2[row] = __expf(f2);
        g_F2[row] = __expf(0.2f * f2);
    }
}

// ---------------------------------------------------------------------------
// Main kernel: fused masked-softmax attention + h' = att @ Wh.
// Software-pipelined: double-buffered ws/Whs, register-held next-tile inputs,
// ONE barrier per j-tile:
//   [issue LDGs(t+1)] -> [stage2 FFMA2 on buf(t)] -> [stage1 -> buf(t+1)] -> bar
// ---------------------------------------------------------------------------
__global__ __launch_bounds__(256) void gat_main(const int* __restrict__ adj,
                                                float* __restrict__ out) {
    __shared__ __align__(16) float2 ws[2][TJ][TI + 1];  // (w,w) pairs
    __shared__ __align__(16) float Whs[2][TJ][HID];
    __shared__ float ls[TI];

    const int tid = threadIdx.x;
    const int lane = tid & 31, wid = tid >> 5;  // stage1 role: j=lane, i=p*8+wid
    const int tx = tid & 7, ty = tid >> 3;      // stage2 role: h=tx*8.., i=ty,ty+32
    const int b = blockIdx.y;
    const int i0 = blockIdx.x * TI;
    const int base = b * N_;

    const int* adjb = adj + (size_t)b * N_ * N_ + (size_t)i0 * N_ + lane;
    const float* Whb = g_Wh + (size_t)base * HID;
    // Whs fill: thread fills rows (tid>>4) and 16+(tid>>4), cols (tid&15)*4
    const int fj = tid >> 4, fh = (tid & 15) << 2;
    const float* whp0 = Whb + (size_t)fj * HID + fh;
    const float* whp1 = Whb + (size_t)(16 + fj) * HID + fh;

    float f1r[8], E1r[8], F1r[8], lacc[8];
#pragma unroll
    for (int p = 0; p < 8; p++) {
        int gi = base + i0 + p * 8 + wid;
        f1r[p] = g_f1[gi];
        E1r[p] = g_E1[gi];
        F1r[p] = g_F1[gi];
        lacc[p] = 0.f;
    }

    unsigned long long acc[2][4];
#pragma unroll
    for (int i = 0; i < 2; i++)
#pragma unroll
        for (int q = 0; q < 4; q++) acc[i][q] = 0ull;

    // ---- prologue: load tile 0, run stage1 into buf 0 ----
    int av[8];
    float f2n, E2n, F2n;
    float4 wh0, wh1;
#pragma unroll
    for (int p = 0; p < 8; p++)
        av[p] = adjb[(size_t)(p * 8 + wid) * N_];
    f2n = g_f2[base + lane];
    E2n = g_E2[base + lane];
    F2n = g_F2[base + lane];
    wh0 = *(const float4*)whp0;
    wh1 = *(const float4*)whp1;

#pragma unroll
    for (int p = 0; p < 8; p++) {
        float x = f1r[p] + f2n;
        float w = (x > 0.f) ? (E1r[p] * E2n) : (F1r[p] * F2n);
        w = (av[p] > 0) ? w : 0.f;
        lacc[p] += w;
        ws[0][lane][p * 8 + wid] = make_float2(w, w);
    }
    *(float4*)&Whs[0][fj][fh]      = wh0;
    *(float4*)&Whs[0][16 + fj][fh] = wh1;
    __syncthreads();

    // ---- main pipelined loop ----
    for (int t = 0; t < NT; t++) {
        const int cur = t & 1, nxt = cur ^ 1;
        const bool more = (t < NT - 1);

        if (more) {
            const int j0n = (t + 1) * TJ;
#pragma unroll
            for (int p = 0; p < 8; p++)
                av[p] = adjb[(size_t)(p * 8 + wid) * N_ + j0n];
            f2n = g_f2[base + j0n + lane];
            E2n = g_E2[base + j0n + lane];
            F2n = g_F2[base + j0n + lane];
            wh0 = *(const float4*)(whp0 + (size_t)j0n * HID);
            wh1 = *(const float4*)(whp1 + (size_t)j0n * HID);
        }

        // stage2: acc += w ⊗ Wh on buffer 'cur' (packed f32x2 FMAs)
#pragma unroll
        for (int j = 0; j < TJ; j++) {
            unsigned long long w0 = *(const unsigned long long*)&ws[cur][j][ty];
            unsigned long long w1 = *(const unsigned long long*)&ws[cur][j][ty + 32];
            ulonglong2 A  = *(const ulonglong2*)&Whs[cur][j][tx * 8];
            ulonglong2 Bv = *(const ulonglong2*)&Whs[cur][j][tx * 8 + 4];
            ffma2(acc[0][0], w0, A.x);
            ffma2(acc[0][1], w0, A.y);
            ffma2(acc[0][2], w0, Bv.x);
            ffma2(acc[0][3], w0, Bv.y);
            ffma2(acc[1][0], w1, A.x);
            ffma2(acc[1][1], w1, A.y);
            ffma2(acc[1][2], w1, Bv.x);
            ffma2(acc[1][3], w1, Bv.y);
        }

        if (more) {
            // stage1 for tile t+1 into buffer 'nxt'
#pragma unroll
            for (int p = 0; p < 8; p++) {
                float x = f1r[p] + f2n;
                float w = (x > 0.f) ? (E1r[p] * E2n) : (F1r[p] * F2n);
                w = (av[p] > 0) ? w : 0.f;
                lacc[p] += w;
                ws[nxt][lane][p * 8 + wid] = make_float2(w, w);
            }
            *(float4*)&Whs[nxt][fj][fh]      = wh0;
            *(float4*)&Whs[nxt][16 + fj][fh] = wh1;
        }
        __syncthreads();
    }

    // ---- softmax denominators + epilogue ----
#pragma unroll
    for (int p = 0; p < 8; p++) {
        float v = lacc[p];
#pragma unroll
        for (int s = 16; s > 0; s >>= 1) v += __shfl_xor_sync(0xffffffffu, v, s);
        if (lane == 0) ls[p * 8 + wid] = v;
    }
    __syncthreads();

    const float r0 = __fdividef(1.f, ls[ty]);
    const float r1 = __fdividef(1.f, ls[ty + 32]);

    float* o0 = out + (size_t)(base + i0 + ty) * HID + tx * 8;
    float* o1 = out + (size_t)(base + i0 + ty + 32) * HID + tx * 8;

    {
        float2 a0 = unpack2(acc[0][0]), a1 = unpack2(acc[0][1]);
        float2 a2 = unpack2(acc[0][2]), a3 = unpack2(acc[0][3]);
        *(float4*)o0       = make_float4(a0.x * r0, a0.y * r0, a1.x * r0, a1.y * r0);
        *(float4*)(o0 + 4) = make_float4(a2.x * r0, a2.y * r0, a3.x * r0, a3.y * r0);
    }
    {
        float2 a0 = unpack2(acc[1][0]), a1 = unpack2(acc[1][1]);
        float2 a2 = unpack2(acc[1][2]), a3 = unpack2(acc[1][3]);
        *(float4*)o1       = make_float4(a0.x * r1, a0.y * r1, a1.x * r1, a1.y * r1);
        *(float4*)(o1 + 4) = make_float4(a2.x * r1, a2.y * r1, a3.x * r1, a3.y * r1);
    }
}

// ---------------------------------------------------------------------------
extern "C" void kernel_launch(void* const* d_in, const int* in_sizes, int n_in,
                              void* d_out, int out_size) {
    const float* X  = (const float*)d_in[0];   // node_features [8,2048,256]
    const int*   A  = (const int*)d_in[1];     // adj [8,2048,2048]
    const float* W  = (const float*)d_in[2];   // W [256,64]
    const float* av = (const float*)d_in[3];   // a [128,1]
    float* out = (float*)d_out;                // [8,2048,64] f32

    gemm_wh<<<(B_ * N_) / 64, 256>>>(X, W);
    compute_f<<<(B_ * N_) / 8, 256>>>(av);
    gat_main<<<dim3(N_ / TI, B_), 256>>>(A, out);
}

// round 4
// speedup vs baseline: 3.7792x; 3.5651x over previous
#include <cuda_runtime.h>
#include <cuda_bf16.h>
#include <cstdint>

#define B_   8
#define N_   2048
#define DIN  256
#define HID  64
#define TI   128
#define CH   32
#define NCH  (N_ / CH)
#define L2E  1.4426950408889634f

// Scratch (device globals — no allocation allowed)
__device__ float    g_Wh[B_ * N_ * HID];            // fp32 row-major (for compute_f)
__device__ uint32_t g_Whh[B_ * N_ * HID / 2];       // bf16x2 hi  [node][h/2]
__device__ uint32_t g_Whl[B_ * N_ * HID / 2];       // bf16x2 lo
__device__ float g_f1e[B_ * N_], g_f1s[B_ * N_];    // f1*log2e, 0.2*f1*log2e
__device__ float g_f2e[B_ * N_], g_f2s[B_ * N_];

// ---------------- helpers ----------------
static __device__ __forceinline__ uint32_t smem_u32(const void* p) {
    uint32_t a;
    asm("{ .reg .u64 t; cvta.to.shared.u64 t, %1; cvt.u32.u64 %0, t; }"
        : "=r"(a) : "l"(p));
    return a;
}
static __device__ __forceinline__ float ex2(float x) {
    float y;
    asm("ex2.approx.f32 %0, %1;" : "=f"(y) : "f"(x));
    return y;
}
// pack two fp32 -> bf16x2 (w0 -> low half, w1 -> high half)
static __device__ __forceinline__ uint32_t pack2(float w0, float w1) {
    uint32_t r;
    asm("cvt.rn.bf16x2.f32 %0, %1, %2;" : "=r"(r) : "f"(w1), "f"(w0));
    return r;
}
// split pair into bf16 hi + bf16 lo (exact residual)
static __device__ __forceinline__ void split2(float w0, float w1,
                                              uint32_t& hi, uint32_t& lo) {
    uint32_t h = pack2(w0, w1);
    float h0 = __uint_as_float(h << 16);
    float h1 = __uint_as_float(h & 0xFFFF0000u);
    lo = pack2(w0 - h0, w1 - h1);
    hi = h;
}
static __device__ __forceinline__ void ldsm4t(uint32_t& r0, uint32_t& r1,
                                              uint32_t& r2, uint32_t& r3,
                                              const void* p) {
    uint32_t a = smem_u32(p);
    asm volatile("ldmatrix.sync.aligned.m8n8.x4.trans.shared.b16 {%0,%1,%2,%3}, [%4];"
                 : "=r"(r0), "=r"(r1), "=r"(r2), "=r"(r3) : "r"(a));
}
static __device__ __forceinline__ void mma16816(float* c, const uint32_t* a,
                                                uint32_t b0, uint32_t b1) {
    asm volatile(
        "mma.sync.aligned.m16n8k16.row.col.f32.bf16.bf16.f32 "
        "{%0,%1,%2,%3}, {%4,%5,%6,%7}, {%8,%9}, {%0,%1,%2,%3};"
        : "+f"(c[0]), "+f"(c[1]), "+f"(c[2]), "+f"(c[3])
        : "r"(a[0]), "r"(a[1]), "r"(a[2]), "r"(a[3]), "r"(b0), "r"(b1));
}

// ---------------------------------------------------------------------------
// Kernel A: Wh = X @ W ; emits fp32 Wh + bf16 hi/lo packed copies.
// ---------------------------------------------------------------------------
__global__ __launch_bounds__(256) void gemm_wh(const float* __restrict__ X,
                                               const float* __restrict__ W) {
    __shared__ __align__(16) float Xs[2][64][36];
    __shared__ __align__(16) float Ws[2][32][64];

    const int tid = threadIdx.x;
    const int tx = tid & 15;
    const int ty = tid >> 4;
    const int r0 = blockIdx.x * 64;
    const int xr = tid >> 3, xk = (tid & 7) << 2;
    const int wk = tid >> 4, wh_ = (tid & 15) << 2;

    float acc[4][4];
#pragma unroll
    for (int i = 0; i < 4; i++)
#pragma unroll
        for (int j = 0; j < 4; j++) acc[i][j] = 0.f;

    float4 xv0, xv1, wv0, wv1;
    xv0 = *(const float4*)(X + (size_t)(r0 + xr) * DIN + xk);
    xv1 = *(const float4*)(X + (size_t)(r0 + 32 + xr) * DIN + xk);
    wv0 = *(const float4*)(W + (size_t)wk * HID + wh_);
    wv1 = *(const float4*)(W + (size_t)(16 + wk) * HID + wh_);
    *(float4*)&Xs[0][xr][xk]      = xv0;
    *(float4*)&Xs[0][32 + xr][xk] = xv1;
    *(float4*)&Ws[0][wk][wh_]      = wv0;
    *(float4*)&Ws[0][16 + wk][wh_] = wv1;
    __syncthreads();

    for (int kt = 0; kt < 8; kt++) {
        const int cur = kt & 1, nxt = cur ^ 1;
        if (kt < 7) {
            const int k0 = (kt + 1) * 32;
            xv0 = *(const float4*)(X + (size_t)(r0 + xr) * DIN + k0 + xk);
            xv1 = *(const float4*)(X + (size_t)(r0 + 32 + xr) * DIN + k0 + xk);
            wv0 = *(const float4*)(W + (size_t)(k0 + wk) * HID + wh_);
            wv1 = *(const float4*)(W + (size_t)(k0 + 16 + wk) * HID + wh_);
        }
#pragma unroll
        for (int k = 0; k < 32; k++) {
            float4 wv = *(float4*)&Ws[cur][k][tx << 2];
#pragma unroll
            for (int rr = 0; rr < 4; rr++) {
                float xv = Xs[cur][(ty << 2) + rr][k];
                acc[rr][0] += xv * wv.x;
                acc[rr][1] += xv * wv.y;
                acc[rr][2] += xv * wv.z;
                acc[rr][3] += xv * wv.w;
            }
        }
        if (kt < 7) {
            *(float4*)&Xs[nxt][xr][xk]      = xv0;
            *(float4*)&Xs[nxt][32 + xr][xk] = xv1;
            *(float4*)&Ws[nxt][wk][wh_]      = wv0;
            *(float4*)&Ws[nxt][16 + wk][wh_] = wv1;
        }
        __syncthreads();
    }

#pragma unroll
    for (int rr = 0; rr < 4; rr++) {
        const int node = r0 + (ty << 2) + rr;
        float4 v = make_float4(acc[rr][0], acc[rr][1], acc[rr][2], acc[rr][3]);
        *(float4*)&g_Wh[(size_t)node * HID + (tx << 2)] = v;
        uint32_t h01, l01, h23, l23;
        split2(v.x, v.y, h01, l01);
        split2(v.z, v.w, h23, l23);
        size_t o = (size_t)node * 32 + tx * 2;
        *(uint2*)&g_Whh[o] = make_uint2(h01, h23);
        *(uint2*)&g_Whl[o] = make_uint2(l01, l23);
    }
}

// ---------------------------------------------------------------------------
// Kernel B: f1/f2 per node, pre-scaled by log2e (and 0.2*log2e).
// ---------------------------------------------------------------------------
__global__ __launch_bounds__(256) void compute_f(const float* __restrict__ a) {
    const int row = blockIdx.x * 8 + (threadIdx.x >> 5);
    const int lane = threadIdx.x & 31;
    const float* wh = g_Wh + (size_t)row * HID;
    float w0 = wh[lane], w1 = wh[lane + 32];
    float f1 = w0 * a[lane] + w1 * a[lane + 32];
    float f2 = w0 * a[HID + lane] + w1 * a[HID + lane + 32];
#pragma unroll
    for (int s = 16; s > 0; s >>= 1) {
        f1 += __shfl_xor_sync(0xffffffffu, f1, s);
        f2 += __shfl_xor_sync(0xffffffffu, f2, s);
    }
    if (lane == 0) {
        g_f1e[row] = f1 * L2E;
        g_f1s[row] = 0.2f * f1 * L2E;
        g_f2e[row] = f2 * L2E;
        g_f2s[row] = 0.2f * f2 * L2E;
    }
}

// ---------------------------------------------------------------------------
// Main kernel: masked-softmax attention * Wh via mma.sync bf16 (2-term split).
// Grid = 128 blocks (b*16 + itile), 8 warps; warp w owns rows w*16..w*16+15.
// A fragments (attention weights) computed directly in mma register layout —
// never touch SMEM. B (Wh bf16 hi/lo) double-buffered in SMEM, 144B-padded
// rows -> conflict-free ldmatrix.x4.trans. One __syncthreads per chunk.
// w = exp2(max(f1e+f2e, f1s+f2s)) masked by adj; softmax denom in registers.
// ---------------------------------------------------------------------------
__global__ __launch_bounds__(256, 1) void gat_main(const int* __restrict__ adj,
                                                   float* __restrict__ out) {
    __shared__ __align__(16) __nv_bfloat16 Bs[2][2][CH][72];  // [buf][split][k][n]

    const int tid = threadIdx.x;
    const int lane = tid & 31, wid = tid >> 5;
    const int g = lane >> 2, tg = lane & 3;
    const int b = blockIdx.x >> 4;
    const int i0 = (blockIdx.x & 15) * TI;
    const int base = b * N_;

    const int r_lo = wid * 16 + g, r_hi = r_lo + 8;

    // B staging: thread covers node fj, h = fh..fh+7 (one uint4 per split)
    const int fj = tid >> 3, fh = (tid & 7) * 8;
    const uint32_t* whh = g_Whh + (size_t)base * 32;
    const uint32_t* whl = g_Whl + (size_t)base * 32;

    const float f1e_lo = g_f1e[base + i0 + r_lo], f1s_lo = g_f1s[base + i0 + r_lo];
    const float f1e_hi = g_f1e[base + i0 + r_hi], f1s_hi = g_f1s[base + i0 + r_hi];
    float dlo = 0.f, dhi = 0.f;

    float c[8][4];
#pragma unroll
    for (int nt = 0; nt < 8; nt++)
#pragma unroll
        for (int q = 0; q < 4; q++) c[nt][q] = 0.f;

    const int* adjlo = adj + (size_t)b * N_ * N_ + (size_t)(i0 + r_lo) * N_;
    const int* adjhi = adjlo + (size_t)8 * N_;

    // ---- prefetch chunk 0 ----
    int2 av[8];  // [s*4 + {lo@2tg, lo@2tg+8, hi@2tg, hi@2tg+8}]
#pragma unroll
    for (int s = 0; s < 2; s++) {
        av[s * 4 + 0] = *(const int2*)&adjlo[s * 16 + 2 * tg];
        av[s * 4 + 1] = *(const int2*)&adjlo[s * 16 + 2 * tg + 8];
        av[s * 4 + 2] = *(const int2*)&adjhi[s * 16 + 2 * tg];
        av[s * 4 + 3] = *(const int2*)&adjhi[s * 16 + 2 * tg + 8];
    }
    float f2e_c = g_f2e[base + lane];
    float f2s_c = g_f2s[base + lane];
    uint4 bhv = *(const uint4*)&whh[(size_t)fj * 32 + (fh >> 1)];
    uint4 blv = *(const uint4*)&whl[(size_t)fj * 32 + (fh >> 1)];

#pragma unroll 2
    for (int t = 0; t < NCH; t++) {
        const int buf = t & 1;

        // store B(t) into SMEM buffer
        *(uint4*)&Bs[buf][0][fj][fh] = bhv;
        *(uint4*)&Bs[buf][1][fj][fh] = blv;

        // issue prefetch for t+1 (latency hides under stage1 + mma)
        const int tn = (t + 1 < NCH) ? t + 1 : t;
        const int j0n = tn * CH;
        int2 nav[8];
#pragma unroll
        for (int s = 0; s < 2; s++) {
            nav[s * 4 + 0] = *(const int2*)&adjlo[j0n + s * 16 + 2 * tg];
            nav[s * 4 + 1] = *(const int2*)&adjlo[j0n + s * 16 + 2 * tg + 8];
            nav[s * 4 + 2] = *(const int2*)&adjhi[j0n + s * 16 + 2 * tg];
            nav[s * 4 + 3] = *(const int2*)&adjhi[j0n + s * 16 + 2 * tg + 8];
        }
        float nf2e = g_f2e[base + j0n + lane];
        float nf2s = g_f2s[base + j0n + lane];
        uint4 nbh = *(const uint4*)&whh[(size_t)(j0n + fj) * 32 + (fh >> 1)];
        uint4 nbl = *(const uint4*)&whl[(size_t)(j0n + fj) * 32 + (fh >> 1)];

        // stage1: attention-weight A-fragments (hi/lo) in mma layout
        uint32_t ah[2][4], al[2][4];
#pragma unroll
        for (int s = 0; s < 2; s++) {
            const int jb = s * 16 + 2 * tg;
            float e0 = __shfl_sync(0xffffffffu, f2e_c, jb);
            float e1 = __shfl_sync(0xffffffffu, f2e_c, jb + 1);
            float e8 = __shfl_sync(0xffffffffu, f2e_c, jb + 8);
            float e9 = __shfl_sync(0xffffffffu, f2e_c, jb + 9);
            float s0 = __shfl_sync(0xffffffffu, f2s_c, jb);
            float s1 = __shfl_sync(0xffffffffu, f2s_c, jb + 1);
            float s8 = __shfl_sync(0xffffffffu, f2s_c, jb + 8);
            float s9 = __shfl_sync(0xffffffffu, f2s_c, jb + 9);

            float wl0 = (av[s * 4 + 0].x > 0) ? ex2(fmaxf(f1e_lo + e0, f1s_lo + s0)) : 0.f;
            float wl1 = (av[s * 4 + 0].y > 0) ? ex2(fmaxf(f1e_lo + e1, f1s_lo + s1)) : 0.f;
            float wl8 = (av[s * 4 + 1].x > 0) ? ex2(fmaxf(f1e_lo + e8, f1s_lo + s8)) : 0.f;
            float wl9 = (av[s * 4 + 1].y > 0) ? ex2(fmaxf(f1e_lo + e9, f1s_lo + s9)) : 0.f;
            float wh0 = (av[s * 4 + 2].x > 0) ? ex2(fmaxf(f1e_hi + e0, f1s_hi + s0)) : 0.f;
            float wh1 = (av[s * 4 + 2].y > 0) ? ex2(fmaxf(f1e_hi + e1, f1s_hi + s1)) : 0.f;
            float wh8 = (av[s * 4 + 3].x > 0) ? ex2(fmaxf(f1e_hi + e8, f1s_hi + s8)) : 0.f;
            float wh9 = (av[s * 4 + 3].y > 0) ? ex2(fmaxf(f1e_hi + e9, f1s_hi + s9)) : 0.f;

            dlo += (wl0 + wl1) + (wl8 + wl9);
            dhi += (wh0 + wh1) + (wh8 + wh9);

            split2(wl0, wl1, ah[s][0], al[s][0]);
            split2(wh0, wh1, ah[s][1], al[s][1]);
            split2(wl8, wl9, ah[s][2], al[s][2]);
            split2(wh8, wh9, ah[s][3], al[s][3]);
        }
        __syncthreads();

        // ldmatrix B fragments + 48 mma (2 ksteps x 4 n16-groups x 3 splits... per pair)
#pragma unroll
        for (int s = 0; s < 2; s++) {
            const int kr = s * 16 + (lane & 15);
            const int nc = ((lane >> 4) << 3);
#pragma unroll
            for (int n16 = 0; n16 < 4; n16++) {
                uint32_t bh0, bh1, bh2, bh3, bl0, bl1, bl2, bl3;
                ldsm4t(bh0, bh1, bh2, bh3, &Bs[buf][0][kr][n16 * 16 + nc]);
                ldsm4t(bl0, bl1, bl2, bl3, &Bs[buf][1][kr][n16 * 16 + nc]);
                mma16816(c[n16 * 2],     ah[s], bh0, bh1);
                mma16816(c[n16 * 2],     al[s], bh0, bh1);
                mma16816(c[n16 * 2],     ah[s], bl0, bl1);
                mma16816(c[n16 * 2 + 1], ah[s], bh2, bh3);
                mma16816(c[n16 * 2 + 1], al[s], bh2, bh3);
                mma16816(c[n16 * 2 + 1], ah[s], bl2, bl3);
            }
        }

        // rotate prefetched values
#pragma unroll
        for (int q = 0; q < 8; q++) av[q] = nav[q];
        f2e_c = nf2e;
        f2s_c = nf2s;
        bhv = nbh;
        blv = nbl;
        adjlo += CH;  // no — keep absolute indexing; see below
        adjlo -= CH;  // (kept absolute via j0n; no pointer bump)
    }

    // ---- softmax denominators (reduce over the 4 lanes sharing a row) ----
    dlo += __shfl_xor_sync(0xffffffffu, dlo, 1);
    dlo += __shfl_xor_sync(0xffffffffu, dlo, 2);
    dhi += __shfl_xor_sync(0xffffffffu, dhi, 1);
    dhi += __shfl_xor_sync(0xffffffffu, dhi, 2);
    const float rlo = __fdividef(1.f, dlo);
    const float rhi = __fdividef(1.f, dhi);

    float* olo = out + (size_t)(base + i0 + r_lo) * HID;
    float* ohi = out + (size_t)(base + i0 + r_hi) * HID;
#pragma unroll
    for (int nt = 0; nt < 8; nt++) {
        *(float2*)&olo[nt * 8 + 2 * tg] = make_float2(c[nt][0] * rlo, c[nt][1] * rlo);
        *(float2*)&ohi[nt * 8 + 2 * tg] = make_float2(c[nt][2] * rhi, c[nt][3] * rhi);
    }
}

// ---------------------------------------------------------------------------
extern "C" void kernel_launch(void* const* d_in, const int* in_sizes, int n_in,
                              void* d_out, int out_size) {
    const float* X  = (const float*)d_in[0];   // node_features [8,2048,256]
    const int*   A  = (const int*)d_in[1];     // adj [8,2048,2048]
    const float* W  = (const float*)d_in[2];   // W [256,64]
    const float* av = (const float*)d_in[3];   // a [128,1]
    float* out = (float*)d_out;                // [8,2048,64] f32

    gemm_wh<<<(B_ * N_) / 64, 256>>>(X, W);
    compute_f<<<(B_ * N_) / 8, 256>>>(av);
    gat_main<<<dim3((B_ * N_) / TI), 256>>>(A, out);
}